// round 16
// baseline (speedup 1.0000x reference)
#include <cuda_runtime.h>
#include <cuda_fp16.h>
#include <math.h>
#include <stdint.h>
#include <string.h>

// ---------------------------------------------------------------------------
// Problem constants
// ---------------------------------------------------------------------------
#define BATCH    2
#define SEQ      2048
#define DMODEL   2048
#define DKV      512
#define DQ       1536
#define NHEADS   16
#define HDIM     128
#define ROWS     (BATCH*SEQ)            // 4096
#define QKDIM    256
#define SCALE    0.0625f                // 1/sqrt(256)

#define OUT_SZ   (BATCH*SEQ*DMODEL)
#define CKV_SZ   (BATCH*SEQ*DKV)

// ---------------------------------------------------------------------------
// Scratch
// ---------------------------------------------------------------------------
__device__ __half g_vT [(size_t)BATCH*DMODEL*SEQ]; // V^T fp16, s-permuted
__device__ __half g_q  [(size_t)BATCH*NHEADS*SEQ*QKDIM]; // fp16, scaled, perm
__device__ __half g_k  [(size_t)BATCH*NHEADS*SEQ*QKDIM]; // fp16, perm
__device__ float2 g_rope[SEQ*64];                  // (cos,sin) per (s,i)

// fp16 GEMM operands
__device__ __half g_h16  [(size_t)ROWS*DMODEL];    // perm32 K-layout
__device__ __half g_cKV16[(size_t)ROWS*DKV];       // perm32 K-layout
__device__ __half g_cQ16 [(size_t)ROWS*DQ];        // perm32 K-layout
__device__ __half g_ctx16[(size_t)ROWS*DMODEL];    // perm32 K-layout
__device__ __half g_qC16 [(size_t)ROWS*DMODEL];    // plain layout (pack input)
__device__ __half g_kC16 [(size_t)ROWS*DMODEL];    // plain layout (pack input)
__device__ __half g_wDKV [(size_t)DKV*DMODEL];     // Wt[N,K]
__device__ __half g_wKR  [(size_t)DMODEL*DMODEL];
__device__ __half g_wDQ  [(size_t)DQ*DMODEL];
__device__ __half g_wUQ  [(size_t)DMODEL*DQ];
__device__ __half g_wUK  [(size_t)DMODEL*DKV];
__device__ __half g_wUV  [(size_t)DMODEL*DKV];
__device__ __half g_wWO  [(size_t)DMODEL*DMODEL];

// fragment-order permutation within 32-element blocks of the reduction dim
__device__ __forceinline__ int perm32(int k) {
    return (k & ~31) | (((k & 7) >> 1) << 3) | (((k >> 3) & 3) << 1) | (k & 1);
}

// ---------------------------------------------------------------------------
// helpers
// ---------------------------------------------------------------------------
__device__ __forceinline__ uint32_t h2_as_u32(__half2 h) {
    uint32_t u;
    memcpy(&u, &h, 4);
    return u;
}

__device__ __forceinline__ void mma_f16(float c[4],
                                        uint32_t a0, uint32_t a1,
                                        uint32_t a2, uint32_t a3,
                                        uint32_t b0, uint32_t b1) {
    asm volatile(
        "mma.sync.aligned.m16n8k16.row.col.f32.f16.f16.f32 "
        "{%0,%1,%2,%3}, {%4,%5,%6,%7}, {%8,%9}, {%0,%1,%2,%3};\n"
        : "+f"(c[0]), "+f"(c[1]), "+f"(c[2]), "+f"(c[3])
        : "r"(a0), "r"(a1), "r"(a2), "r"(a3), "r"(b0), "r"(b1));
}

__device__ __forceinline__ void cp_async16(void* smem_dst, const void* gsrc) {
    uint32_t sa = (uint32_t)__cvta_generic_to_shared(smem_dst);
    asm volatile("cp.async.cg.shared.global [%0], [%1], 16;\n"
                 :: "r"(sa), "l"(gsrc));
}
__device__ __forceinline__ void cp_commit() {
    asm volatile("cp.async.commit_group;\n" ::: "memory");
}
__device__ __forceinline__ void cp_wait1() {
    asm volatile("cp.async.wait_group 1;\n" ::: "memory");
}

// ---------------------------------------------------------------------------
// Rope table
// ---------------------------------------------------------------------------
__global__ __launch_bounds__(256) void rope_table_kernel(float2* __restrict__ t)
{
    int idx = blockIdx.x * 256 + threadIdx.x;
    int i = idx & 63;
    int s = idx >> 6;
    float inv = powf(10000.0f, -(float)(2 * i) / 128.0f);
    float sn, cs; sincosf((float)s * inv, &sn, &cs);
    t[idx] = make_float2(cs, sn);
}

// ---------------------------------------------------------------------------
// Convert h -> fp16 (perm32 on columns)
// ---------------------------------------------------------------------------
__global__ __launch_bounds__(256) void conv_h_kernel(
    const float* __restrict__ src, __half* __restrict__ dst)
{
    int idx = blockIdx.x * 256 + threadIdx.x;
    int c = idx & (DMODEL - 1);
    int r = idx >> 11;
    dst[(size_t)r * DMODEL + perm32(c)] = __float2half(src[idx]);
}

// ---------------------------------------------------------------------------
// Convert+transpose weight: W[K,N] fp32 -> Wt[N,K] fp16 (perm32 on K)
// ---------------------------------------------------------------------------
__global__ __launch_bounds__(256) void conv_wt_kernel(
    const float* __restrict__ W, __half* __restrict__ Wt, int K, int N)
{
    __shared__ float tile[32][33];
    int k0 = blockIdx.y * 32, n0 = blockIdx.x * 32;
    int tx = threadIdx.x & 31, ty = threadIdx.x >> 5;
#pragma unroll
    for (int j = 0; j < 4; j++)
        tile[ty + 8 * j][tx] = W[(size_t)(k0 + ty + 8 * j) * N + n0 + tx];
    __syncthreads();
#pragma unroll
    for (int j = 0; j < 4; j++) {
        int n = n0 + ty + 8 * j;
        Wt[(size_t)n * K + k0 + perm32(tx)] = __float2half(tile[tx][ty + 8 * j]);
    }
}

// ---------------------------------------------------------------------------
// FP16 tensor-core GEMM: C[M,N] = A[M,K] @ Bt[N,K]^T + bias[N]
// 256 threads, 8 warps (4 M x 2 N), warp tile 32x64, BM=BN=128, BK=64,
// 2-stage cp.async, 2 CTAs/SM (16 warps/SM for latency cover).
// mode bits: 1 = fp32 Cf, 2 = fp16 perm32(col) Ch, 32 = fp16 plain Ch,
//            4 = fp16 vT layout via smem-staged coalesced stores
// ---------------------------------------------------------------------------
#define HBK    64
#define H_LDH  96
#define HSTAGE (256*H_LDH)
#define HGEMM_SMEM (2*HSTAGE*2)           // 98304 bytes
#define VSTG_LD 136

__device__ __forceinline__ void h_load_stage(
    __half* As, __half* Bs,
    const __half* __restrict__ Ab, const __half* __restrict__ Bb,
    int k0, int K, int tid)
{
#pragma unroll
    for (int i = 0; i < 4; i++) {
        int c = tid + 256 * i;            // 1024 chunks of 16B
        int r = c >> 3, off = (c & 7) * 8;
        cp_async16(As + r * H_LDH + off, Ab + (size_t)r * K + k0 + off);
    }
#pragma unroll
    for (int i = 0; i < 4; i++) {
        int c = tid + 256 * i;
        int r = c >> 3, off = (c & 7) * 8;
        cp_async16(Bs + r * H_LDH + off, Bb + (size_t)r * K + k0 + off);
    }
}

__global__ __launch_bounds__(256, 2) void f16_gemm(
    int M, int N, int K,
    const __half* __restrict__ A, const __half* __restrict__ Bt,
    const float* __restrict__ bias,
    float* __restrict__ Cf, __half* __restrict__ Ch, int mode)
{
    extern __shared__ __half hsm[];

    const int tid  = threadIdx.x;
    const int bx   = blockIdx.x, by = blockIdx.y;
    const int warp = tid >> 5, lane = tid & 31;
    const int wm   = (warp >> 1) * 32;    // 4 warps over M, 32 rows each
    const int wn   = (warp & 1) * 64;     // 2 warps over N, 64 cols each
    const int g    = lane >> 2;
    const int tg   = lane & 3;

    const __half* Ab = A  + (size_t)(by * 128) * K;
    const __half* Bb = Bt + (size_t)(bx * 128) * K;

    float acc[2][8][4];
#pragma unroll
    for (int mt = 0; mt < 2; mt++)
#pragma unroll
        for (int nt = 0; nt < 8; nt++)
#pragma unroll
            for (int i = 0; i < 4; i++) acc[mt][nt][i] = 0.f;

    h_load_stage(hsm, hsm + 128 * H_LDH, Ab, Bb, 0, K, tid);
    cp_commit();
    if (HBK < K)
        h_load_stage(hsm + HSTAGE, hsm + HSTAGE + 128 * H_LDH, Ab, Bb, HBK, K, tid);
    cp_commit();

    int rs = 0;
    for (int k0 = 0; k0 < K; k0 += HBK) {
        cp_wait1();
        __syncthreads();

        __half* As = hsm + rs * HSTAGE;
        __half* Bs = As + 128 * H_LDH;

#pragma unroll
        for (int kb = 0; kb < 2; kb++) {
            uint4 aL[2], aH[2];
#pragma unroll
            for (int mt = 0; mt < 2; mt++) {
                aL[mt] = *(const uint4*)(As + (wm + mt * 16 + g)     * H_LDH + kb * 32 + 8 * tg);
                aH[mt] = *(const uint4*)(As + (wm + mt * 16 + g + 8) * H_LDH + kb * 32 + 8 * tg);
            }
#pragma unroll
            for (int nt = 0; nt < 8; nt++) {
                uint4 bv = *(const uint4*)(Bs + (wn + nt * 8 + g) * H_LDH + kb * 32 + 8 * tg);
#pragma unroll
                for (int mt = 0; mt < 2; mt++) {
                    mma_f16(acc[mt][nt], aL[mt].x, aH[mt].x, aL[mt].y, aH[mt].y, bv.x, bv.y);
                    mma_f16(acc[mt][nt], aL[mt].z, aH[mt].z, aL[mt].w, aH[mt].w, bv.z, bv.w);
                }
            }
        }

        __syncthreads();
        int kl = k0 + 2 * HBK;
        if (kl < K)
            h_load_stage(As, Bs, Ab, Bb, kl, K, tid);
        cp_commit();
        rs ^= 1;
    }

    if (mode & 4) {
        // vT epilogue: stage [128 d][perm32(s)] fp16 tile, then coalesce
        __half* stg = hsm;
#pragma unroll
        for (int mt = 0; mt < 2; mt++) {
            int sl_lo = wm + mt * 16 + g;
            int sl_hi = sl_lo + 8;
            int ps_lo = perm32(sl_lo), ps_hi = perm32(sl_hi);
#pragma unroll
            for (int nt = 0; nt < 8; nt++) {
                int cl = wn + nt * 8 + 2 * tg;
                float b0 = bias[bx * 128 + cl], b1 = bias[bx * 128 + cl + 1];
                stg[(cl)     * VSTG_LD + ps_lo] = __float2half(acc[mt][nt][0] + b0);
                stg[(cl + 1) * VSTG_LD + ps_lo] = __float2half(acc[mt][nt][1] + b1);
                stg[(cl)     * VSTG_LD + ps_hi] = __float2half(acc[mt][nt][2] + b0);
                stg[(cl + 1) * VSTG_LD + ps_hi] = __float2half(acc[mt][nt][3] + b1);
            }
        }
        __syncthreads();
        int bb = (by * 128) >> 11;
        int s0 = (by * 128) & (SEQ - 1);
        __half* vbase = Ch + ((size_t)bb * N + bx * 128) * SEQ + s0;
#pragma unroll
        for (int i = 0; i < 8; i++) {
            int c = tid + 256 * i;             // 2048 chunks of 8 halves
            int cl = c >> 4, off = (c & 15) * 8;
            *(uint4*)(vbase + (size_t)cl * SEQ + off) =
                *(const uint4*)(stg + cl * VSTG_LD + off);
        }
        return;
    }

#pragma unroll
    for (int mt = 0; mt < 2; mt++) {
        int r_lo = by * 128 + wm + mt * 16 + g;
        int r_hi = r_lo + 8;
#pragma unroll
        for (int nt = 0; nt < 8; nt++) {
            int col = bx * 128 + wn + nt * 8 + 2 * tg;
            float b0 = bias[col], b1 = bias[col + 1];
            float v00 = acc[mt][nt][0] + b0, v01 = acc[mt][nt][1] + b1;
            float v10 = acc[mt][nt][2] + b0, v11 = acc[mt][nt][3] + b1;
            if (mode & 1) {
                *(float2*)(&Cf[(size_t)r_lo * N + col]) = make_float2(v00, v01);
                *(float2*)(&Cf[(size_t)r_hi * N + col]) = make_float2(v10, v11);
            }
            if (mode & 2) {
                int pc = perm32(col);
                *(__half2*)(&Ch[(size_t)r_lo * N + pc]) = __floats2half2_rn(v00, v01);
                *(__half2*)(&Ch[(size_t)r_hi * N + pc]) = __floats2half2_rn(v10, v11);
            }
            if (mode & 32) {
                *(__half2*)(&Ch[(size_t)r_lo * N + col]) = __floats2half2_rn(v00, v01);
                *(__half2*)(&Ch[(size_t)r_hi * N + col]) = __floats2half2_rn(v10, v11);
            }
        }
    }
}

// ---------------------------------------------------------------------------
// Pack q (fp16 in, fp16 out, scaled, perm32 on k-dim)
// ---------------------------------------------------------------------------
__global__ __launch_bounds__(256) void pack_q_kernel(
    const __half* __restrict__ qC, const float2* __restrict__ rope,
    __half* __restrict__ q)
{
    int gid = blockIdx.x * blockDim.x + threadIdx.x;
    int i = gid & 63;
    int s = (gid >> 6) & (SEQ - 1);
    int h = (gid >> 17) & (NHEADS - 1);
    int b = gid >> 21;

    const __half2* src = (const __half2*)(qC + ((size_t)(b * SEQ + s)) * DMODEL + h * HDIM);
    float2 x = __half22float2(src[i]);

    float2 cssn = rope[s * 64 + i];
    float cs = cssn.x, sn = cssn.y;

    __half* dst = q + (((size_t)(b * NHEADS + h)) * SEQ + s) * QKDIM;
    dst[perm32(2 * i)]       = __float2half(x.x * SCALE);
    dst[perm32(2 * i + 1)]   = __float2half(x.y * SCALE);
    dst[perm32(128 + 2 * i)] = __float2half((x.x * cs - x.y * sn) * SCALE);
    dst[perm32(129 + 2 * i)] = __float2half((x.x * sn + x.y * cs) * SCALE);
}

// ---------------------------------------------------------------------------
// Pack k (fp16 raw in, fp32 kr in, fp16 out, perm32 on k-dim)
// ---------------------------------------------------------------------------
__global__ __launch_bounds__(256) void pack_k_kernel(
    const __half* __restrict__ kC, const float* __restrict__ kr,
    const float2* __restrict__ rope, __half* __restrict__ k)
{
    int gid = blockIdx.x * blockDim.x + threadIdx.x;
    int i = gid & 63;
    int s = (gid >> 6) & (SEQ - 1);
    int h = (gid >> 17) & (NHEADS - 1);
    int b = gid >> 21;

    size_t soff = ((size_t)(b * SEQ + s)) * DMODEL + h * HDIM;
    const __half2* raw = (const __half2*)(kC + soff);
    float2 x = __half22float2(raw[i]);
    float2 rot = *(const float2*)(kr + soff + 2 * i);

    float2 cssn = rope[s * 64 + i];
    float cs = cssn.x, sn = cssn.y;

    __half* dst = k + (((size_t)(b * NHEADS + h)) * SEQ + s) * QKDIM;
    dst[perm32(2 * i)]       = __float2half(x.x);
    dst[perm32(2 * i + 1)]   = __float2half(x.y);
    dst[perm32(128 + 2 * i)] = __float2half(rot.x * cs - rot.y * sn);
    dst[perm32(129 + 2 * i)] = __float2half(rot.x * sn + rot.y * cs);
}

// ---------------------------------------------------------------------------
// FP16 flash attention.  BM=128 (8 M-warps x 16 rows), BN=64, 256 threads.
// Q and P in registers.  K and V double-buffered: 2 syncs/iter.  (R13)
// ---------------------------------------------------------------------------
#define K_LDH 288
#define V_LDH 96
#define KBUF  (64*K_LDH)
#define VBUF  (128*V_LDH)
#define FL_SMEM ((2*KBUF + 2*VBUF) * 2)   // 122880 bytes

__global__ __launch_bounds__(256, 1) void flash_f16(
    const __half* __restrict__ q,
    const __half* __restrict__ kk,
    const __half* __restrict__ vT,
    __half* __restrict__ ctx16)
{
    extern __shared__ __half smh[];
    __half* ksb = smh;
    __half* vsb = smh + 2 * KBUF;

    const int tid  = threadIdx.x;
    const int warp = tid >> 5, lane = tid & 31;
    const int g    = lane >> 2;
    const int tg   = lane & 3;
    const int wm   = warp * 16;

    const int qt = 15 - blockIdx.x;
    const int bh = blockIdx.y;
    const int b = bh >> 4, h = bh & 15;
    const int kmax = 2 * qt + 2;

    const __half* vtb_base = vT + ((size_t)b * DMODEL + h * HDIM) * SEQ;
    const __half* kbh      = kk + ((size_t)bh * SEQ) * QKDIM;

    const int rg0 = qt * 128 + wm + g;
    const int rg1 = rg0 + 8;
    uint4 qlo[8], qhi[8];
    {
        const uint4* q0 = (const uint4*)(q + ((size_t)bh * SEQ + rg0) * QKDIM) + tg;
        const uint4* q1 = (const uint4*)(q + ((size_t)bh * SEQ + rg1) * QKDIM) + tg;
#pragma unroll
        for (int kb = 0; kb < 8; kb++) {
            qlo[kb] = q0[kb * 4];
            qhi[kb] = q1[kb * 4];
        }
    }

#pragma unroll
    for (int st = 0; st < 2; st++) {
        if (st < kmax) {
            const __half* kb = kbh + (size_t)(st * 64) * QKDIM;
            __half* ks = ksb + st * KBUF;
#pragma unroll
            for (int i = 0; i < 8; i++) {
                int c = tid + 256 * i;
                int r = c >> 5, off = (c & 31) * 8;
                cp_async16(ks + r * K_LDH + off, kb + (size_t)r * QKDIM + off);
            }
            const __half* vb = vtb_base + st * 64;
            __half* vs = vsb + st * VBUF;
#pragma unroll
            for (int i = 0; i < 4; i++) {
                int c = tid + 256 * i;
                int r = c >> 3, off = (c & 7) * 8;
                cp_async16(vs + r * V_LDH + off, vb + (size_t)r * SEQ + off);
            }
        }
        cp_commit();
    }

    float m0 = -1e30f, m1 = -1e30f, l0 = 0.f, l1 = 0.f;
    float oacc[16][4];
#pragma unroll
    for (int nt = 0; nt < 16; nt++)
#pragma unroll
        for (int i = 0; i < 4; i++) oacc[nt][i] = 0.f;

    for (int kt = 0; kt < kmax; kt++) {
        cp_wait1();
        __syncthreads();

        const __half* ks = ksb + (kt & 1) * KBUF;
        const __half* vs = vsb + (kt & 1) * VBUF;

        float sacc[8][4];
#pragma unroll
        for (int nt = 0; nt < 8; nt++)
#pragma unroll
            for (int i = 0; i < 4; i++) sacc[nt][i] = 0.f;

#pragma unroll
        for (int kb = 0; kb < 8; kb++) {
            uint4 L = qlo[kb], H = qhi[kb];
#pragma unroll
            for (int nt = 0; nt < 8; nt++) {
                uint4 kv = *(const uint4*)(ks + (8 * nt + g) * K_LDH + kb * 32 + 8 * tg);
                mma_f16(sacc[nt], L.x, H.x, L.y, H.y, kv.x, kv.y);
                mma_f16(sacc[nt], L.z, H.z, L.w, H.w, kv.z, kv.w);
            }
        }

        if (kt >= 2 * qt) {
            int cb = kt * 64 + 2 * tg;
#pragma unroll
            for (int nt = 0; nt < 8; nt++) {
                int c0 = cb + 8 * nt, c1 = c0 + 1;
                if (c0 > rg0) sacc[nt][0] = -1e30f;
                if (c1 > rg0) sacc[nt][1] = -1e30f;
                if (c0 > rg1) sacc[nt][2] = -1e30f;
                if (c1 > rg1) sacc[nt][3] = -1e30f;
            }
        }

        float tA = -1e30f, tB = -1e30f;
#pragma unroll
        for (int nt = 0; nt < 8; nt++) {
            tA = fmaxf(tA, fmaxf(sacc[nt][0], sacc[nt][1]));
            tB = fmaxf(tB, fmaxf(sacc[nt][2], sacc[nt][3]));
        }
        tA = fmaxf(tA, __shfl_xor_sync(0xffffffffu, tA, 1));
        tA = fmaxf(tA, __shfl_xor_sync(0xffffffffu, tA, 2));
        tB = fmaxf(tB, __shfl_xor_sync(0xffffffffu, tB, 1));
        tB = fmaxf(tB, __shfl_xor_sync(0xffffffffu, tB, 2));

        float mn0 = fmaxf(m0, tA), mn1 = fmaxf(m1, tB);
        float f0 = __expf(m0 - mn0), f1 = __expf(m1 - mn1);
        m0 = mn0; m1 = mn1;

        float sum0 = 0.f, sum1 = 0.f;
        uint32_t ph01[8], ph23[8];
#pragma unroll
        for (int nt = 0; nt < 8; nt++) {
            float p0 = __expf(sacc[nt][0] - mn0);
            float p1 = __expf(sacc[nt][1] - mn0);
            float p2 = __expf(sacc[nt][2] - mn1);
            float p3 = __expf(sacc[nt][3] - mn1);
            sum0 += p0 + p1;
            sum1 += p2 + p3;
            ph01[nt] = h2_as_u32(__floats2half2_rn(p0, p1));
            ph23[nt] = h2_as_u32(__floats2half2_rn(p2, p3));
        }
        sum0 += __shfl_xor_sync(0xffffffffu, sum0, 1);
        sum0 += __shfl_xor_sync(0xffffffffu, sum0, 2);
        sum1 += __shfl_xor_sync(0xffffffffu, sum1, 1);
        sum1 += __shfl_xor_sync(0xffffffffu, sum1, 2);
        l0 = l0 * f0 + sum0;
        l1 = l1 * f1 + sum1;

#pragma unroll
        for (int nt = 0; nt < 16; nt++) {
            oacc[nt][0] *= f0; oacc[nt][1] *= f0;
            oacc[nt][2] *= f1; oacc[nt][3] *= f1;
        }
#pragma unroll
        for (int kb = 0; kb < 2; kb++) {
            uint32_t aL0 = ph01[4 * kb + 0], aL1 = ph23[4 * kb + 0];
            uint32_t aL2 = ph01[4 * kb + 1], aL3 = ph23[4 * kb + 1];
            uint32_t aH0 = ph01[4 * kb + 2], aH1 = ph23[4 * kb + 2];
            uint32_t aH2 = ph01[4 * kb + 3], aH3 = ph23[4 * kb + 3];
#pragma unroll
            for (int nt = 0; nt < 16; nt++) {
                uint4 vv = *(const uint4*)(vs + (8 * nt + g) * V_LDH + kb * 32 + 8 * tg);
                mma_f16(oacc[nt], aL0, aL1, aL2, aL3, vv.x, vv.y);
                mma_f16(oacc[nt], aH0, aH1, aH2, aH3, vv.z, vv.w);
            }
        }

        __syncthreads();

        if (kt + 2 < kmax) {
            const __half* kb = kbh + (size_t)((kt + 2) * 64) * QKDIM;
            __half* ksn = ksb + (kt & 1) * KBUF;
#pragma unroll
            for (int i = 0; i < 8; i++) {
                int c = tid + 256 * i;
                int r = c >> 5, off = (c & 31) * 8;
                cp_async16(ksn + r * K_LDH + off, kb + (size_t)r * QKDIM + off);
            }
            const __half* vb = vtb_base + (kt + 2) * 64;
            __half* vsn = vsb + (kt & 1) * VBUF;
#pragma unroll
            for (int i = 0; i < 4; i++) {
                int c = tid + 256 * i;
                int r = c >> 3, off = (c & 7) * 8;
                cp_async16(vsn + r * V_LDH + off, vb + (size_t)r * SEQ + off);
            }
        }
        cp_commit();
    }

    float inv0 = 1.f / l0, inv1 = 1.f / l1;
    __half* o0 = ctx16 + ((size_t)b * SEQ + rg0) * DMODEL + h * HDIM;
    __half* o1 = ctx16 + ((size_t)b * SEQ + rg1) * DMODEL + h * HDIM;
#pragma unroll
    for (int nt = 0; nt < 16; nt++) {
        int c = 8 * nt + 2 * tg;
        int pc = perm32(c);
        *(__half2*)(o0 + pc) = __floats2half2_rn(oacc[nt][0] * inv0, oacc[nt][1] * inv0);
        *(__half2*)(o1 + pc) = __floats2half2_rn(oacc[nt][2] * inv1, oacc[nt][3] * inv1);
    }
}

// ---------------------------------------------------------------------------
// Launch
// ---------------------------------------------------------------------------
extern "C" void kernel_launch(void* const* d_in, const int* in_sizes, int n_in,
                              void* d_out, int out_size)
{
    const float* h     = (const float*)d_in[0];
    const float* W_DKV = (const float*)d_in[1];
    const float* b_DKV = (const float*)d_in[2];
    const float* W_UK  = (const float*)d_in[3];
    const float* b_UK  = (const float*)d_in[4];
    const float* W_UV  = (const float*)d_in[5];
    const float* b_UV  = (const float*)d_in[6];
    const float* W_DQ  = (const float*)d_in[7];
    const float* b_DQ  = (const float*)d_in[8];
    const float* W_UQ  = (const float*)d_in[9];
    const float* b_UQ  = (const float*)d_in[10];
    const float* W_KR  = (const float*)d_in[11];
    const float* b_KR  = (const float*)d_in[12];
    const float* W_O   = (const float*)d_in[13];
    const float* b_O   = (const float*)d_in[14];

    float* out = (float*)d_out;
    float* cKV = out + OUT_SZ;
    float* kr  = cKV + CKV_SZ;

    float2* p_rope;
    __half *p_vT, *p_q, *p_k;
    __half *p_h16, *p_cKV16, *p_cQ16, *p_ctx16, *p_qC16, *p_kC16;
    __half *p_wDKV, *p_wKR, *p_wDQ, *p_wUQ, *p_wUK, *p_wUV, *p_wWO;
    cudaGetSymbolAddress((void**)&p_vT,    g_vT);
    cudaGetSymbolAddress((void**)&p_q,     g_q);
    cudaGetSymbolAddress((void**)&p_k,     g_k);
    cudaGetSymbolAddress((void**)&p_rope,  g_rope);
    cudaGetSymbolAddress((void**)&p_h16,   g_h16);
    cudaGetSymbolAddress((void**)&p_cKV16, g_cKV16);
    cudaGetSymbolAddress((void**)&p_cQ16,  g_cQ16);
    cudaGetSymbolAddress((void**)&p_ctx16, g_ctx16);
    cudaGetSymbolAddress((void**)&p_qC16,  g_qC16);
    cudaGetSymbolAddress((void**)&p_kC16,  g_kC16);
    cudaGetSymbolAddress((void**)&p_wDKV,  g_wDKV);
    cudaGetSymbolAddress((void**)&p_wKR,   g_wKR);
    cudaGetSymbolAddress((void**)&p_wDQ,   g_wDQ);
    cudaGetSymbolAddress((void**)&p_wUQ,   g_wUQ);
    cudaGetSymbolAddress((void**)&p_wUK,   g_wUK);
    cudaGetSymbolAddress((void**)&p_wUV,   g_wUV);
    cudaGetSymbolAddress((void**)&p_wWO,   g_wWO);

    cudaFuncSetAttribute(f16_gemm,
                         cudaFuncAttributeMaxDynamicSharedMemorySize, HGEMM_SMEM);
    cudaFuncSetAttribute(flash_f16,
                         cudaFuncAttributeMaxDynamicSharedMemorySize, FL_SMEM);

    int pack_threads = BATCH * NHEADS * SEQ * 64;

    // setup
    rope_table_kernel<<<(SEQ * 64) / 256, 256>>>(p_rope);
    conv_h_kernel<<<(ROWS * DMODEL) / 256, 256>>>(h, p_h16);
    conv_wt_kernel<<<dim3(DKV/32,    DMODEL/32), 256>>>(W_DKV, p_wDKV, DMODEL, DKV);
    conv_wt_kernel<<<dim3(DMODEL/32, DMODEL/32), 256>>>(W_KR,  p_wKR,  DMODEL, DMODEL);
    conv_wt_kernel<<<dim3(DQ/32,     DMODEL/32), 256>>>(W_DQ,  p_wDQ,  DMODEL, DQ);
    // DKV GEMM  <-- ncu capture slot
    f16_gemm<<<dim3(DKV/128,    ROWS/128), 256, HGEMM_SMEM>>>(ROWS, DKV,    DMODEL, p_h16, p_wDKV, b_DKV, cKV, p_cKV16, 3);
    conv_wt_kernel<<<dim3(DMODEL/32, DQ/32),     256>>>(W_UQ, p_wUQ, DQ,  DMODEL);
    conv_wt_kernel<<<dim3(DMODEL/32, DKV/32),    256>>>(W_UK, p_wUK, DKV, DMODEL);
    conv_wt_kernel<<<dim3(DMODEL/32, DKV/32),    256>>>(W_UV, p_wUV, DKV, DMODEL);
    conv_wt_kernel<<<dim3(DMODEL/32, DMODEL/32), 256>>>(W_O,  p_wWO, DMODEL, DMODEL);
    // projections
    f16_gemm<<<dim3(DMODEL/128, ROWS/128), 256, HGEMM_SMEM>>>(ROWS, DMODEL, DMODEL, p_h16,   p_wKR, b_KR, kr,   (__half*)0, 1);
    f16_gemm<<<dim3(DQ/128,     ROWS/128), 256, HGEMM_SMEM>>>(ROWS, DQ,     DMODEL, p_h16,   p_wDQ, b_DQ, (float*)0, p_cQ16, 2);
    f16_gemm<<<dim3(DMODEL/128, ROWS/128), 256, HGEMM_SMEM>>>(ROWS, DMODEL, DQ,     p_cQ16,  p_wUQ, b_UQ, (float*)0, p_qC16, 32);
    pack_q_kernel<<<pack_threads / 256, 256>>>(p_qC16, p_rope, p_q);
    f16_gemm<<<dim3(DMODEL/128, ROWS/128), 256, HGEMM_SMEM>>>(ROWS, DMODEL, DKV,    p_cKV16, p_wUK, b_UK, (float*)0, p_kC16, 32);
    f16_gemm<<<dim3(DMODEL/128, ROWS/128), 256, HGEMM_SMEM>>>(ROWS, DMODEL, DKV,    p_cKV16, p_wUV, b_UV, (float*)0, p_vT, 4);
    pack_k_kernel<<<pack_threads / 256, 256>>>(p_kC16, kr, p_rope, p_k);
    // attention
    flash_f16<<<dim3(16, BATCH*NHEADS), 256, FL_SMEM>>>(p_q, p_k, p_vT, p_ctx16);
    // output projection
    f16_gemm<<<dim3(DMODEL/128, ROWS/128), 256, HGEMM_SMEM>>>(ROWS, DMODEL, DMODEL, p_ctx16, p_wWO, b_O, out, (__half*)0, 1);
}

// round 17
// speedup vs baseline: 1.1146x; 1.1146x over previous
#include <cuda_runtime.h>
#include <cuda_fp16.h>
#include <math.h>
#include <stdint.h>
#include <string.h>

// ---------------------------------------------------------------------------
// Problem constants
// ---------------------------------------------------------------------------
#define BATCH    2
#define SEQ      2048
#define DMODEL   2048
#define DKV      512
#define DQ       1536
#define NHEADS   16
#define HDIM     128
#define ROWS     (BATCH*SEQ)            // 4096
#define QKDIM    256
#define SCALE    0.0625f                // 1/sqrt(256)

#define OUT_SZ   (BATCH*SEQ*DMODEL)
#define CKV_SZ   (BATCH*SEQ*DKV)

// ---------------------------------------------------------------------------
// Scratch
// ---------------------------------------------------------------------------
__device__ __half g_vT [(size_t)BATCH*DMODEL*SEQ]; // V^T fp16, s-permuted
__device__ __half g_q  [(size_t)BATCH*NHEADS*SEQ*QKDIM]; // fp16, scaled, perm
__device__ __half g_k  [(size_t)BATCH*NHEADS*SEQ*QKDIM]; // fp16, perm
__device__ float2 g_rope[SEQ*64];                  // (cos,sin) per (s,i)

// fp16 GEMM operands
__device__ __half g_h16  [(size_t)ROWS*DMODEL];    // perm32 K-layout
__device__ __half g_cKV16[(size_t)ROWS*DKV];       // perm32 K-layout
__device__ __half g_cQ16 [(size_t)ROWS*DQ];        // perm32 K-layout
__device__ __half g_ctx16[(size_t)ROWS*DMODEL];    // perm32 K-layout
__device__ __half g_qC16 [(size_t)ROWS*DMODEL];    // plain layout (pack input)
__device__ __half g_kC16 [(size_t)ROWS*DMODEL];    // plain layout (pack input)
__device__ __half g_wDKV [(size_t)DKV*DMODEL];     // Wt[N,K]
__device__ __half g_wKR  [(size_t)DMODEL*DMODEL];
__device__ __half g_wDQ  [(size_t)DQ*DMODEL];
__device__ __half g_wUQ  [(size_t)DMODEL*DQ];
__device__ __half g_wUK  [(size_t)DMODEL*DKV];
__device__ __half g_wUV  [(size_t)DMODEL*DKV];
__device__ __half g_wWO  [(size_t)DMODEL*DMODEL];

// fragment-order permutation within 32-element blocks of the reduction dim
__device__ __forceinline__ int perm32(int k) {
    return (k & ~31) | (((k & 7) >> 1) << 3) | (((k >> 3) & 3) << 1) | (k & 1);
}

// ---------------------------------------------------------------------------
// helpers
// ---------------------------------------------------------------------------
__device__ __forceinline__ uint32_t h2_as_u32(__half2 h) {
    uint32_t u;
    memcpy(&u, &h, 4);
    return u;
}

__device__ __forceinline__ void mma_f16(float c[4],
                                        uint32_t a0, uint32_t a1,
                                        uint32_t a2, uint32_t a3,
                                        uint32_t b0, uint32_t b1) {
    asm volatile(
        "mma.sync.aligned.m16n8k16.row.col.f32.f16.f16.f32 "
        "{%0,%1,%2,%3}, {%4,%5,%6,%7}, {%8,%9}, {%0,%1,%2,%3};\n"
        : "+f"(c[0]), "+f"(c[1]), "+f"(c[2]), "+f"(c[3])
        : "r"(a0), "r"(a1), "r"(a2), "r"(a3), "r"(b0), "r"(b1));
}

__device__ __forceinline__ void cp_async16(void* smem_dst, const void* gsrc) {
    uint32_t sa = (uint32_t)__cvta_generic_to_shared(smem_dst);
    asm volatile("cp.async.cg.shared.global [%0], [%1], 16;\n"
                 :: "r"(sa), "l"(gsrc));
}
__device__ __forceinline__ void cp_commit() {
    asm volatile("cp.async.commit_group;\n" ::: "memory");
}
__device__ __forceinline__ void cp_wait1() {
    asm volatile("cp.async.wait_group 1;\n" ::: "memory");
}

// ---------------------------------------------------------------------------
// Rope table
// ---------------------------------------------------------------------------
__global__ __launch_bounds__(256) void rope_table_kernel(float2* __restrict__ t)
{
    int idx = blockIdx.x * 256 + threadIdx.x;
    int i = idx & 63;
    int s = idx >> 6;
    float inv = powf(10000.0f, -(float)(2 * i) / 128.0f);
    float sn, cs; sincosf((float)s * inv, &sn, &cs);
    t[idx] = make_float2(cs, sn);
}

// ---------------------------------------------------------------------------
// Convert h -> fp16 (perm32 on columns)
// ---------------------------------------------------------------------------
__global__ __launch_bounds__(256) void conv_h_kernel(
    const float* __restrict__ src, __half* __restrict__ dst)
{
    int idx = blockIdx.x * 256 + threadIdx.x;
    int c = idx & (DMODEL - 1);
    int r = idx >> 11;
    dst[(size_t)r * DMODEL + perm32(c)] = __float2half(src[idx]);
}

// ---------------------------------------------------------------------------
// Convert+transpose weight: W[K,N] fp32 -> Wt[N,K] fp16 (perm32 on K)
// ---------------------------------------------------------------------------
__global__ __launch_bounds__(256) void conv_wt_kernel(
    const float* __restrict__ W, __half* __restrict__ Wt, int K, int N)
{
    __shared__ float tile[32][33];
    int k0 = blockIdx.y * 32, n0 = blockIdx.x * 32;
    int tx = threadIdx.x & 31, ty = threadIdx.x >> 5;
#pragma unroll
    for (int j = 0; j < 4; j++)
        tile[ty + 8 * j][tx] = W[(size_t)(k0 + ty + 8 * j) * N + n0 + tx];
    __syncthreads();
#pragma unroll
    for (int j = 0; j < 4; j++) {
        int n = n0 + ty + 8 * j;
        Wt[(size_t)n * K + k0 + perm32(tx)] = __float2half(tile[tx][ty + 8 * j]);
    }
}

// ---------------------------------------------------------------------------
// FP16 tensor-core GEMM body (R13 config): 128 threads, 4 warps (2x2),
// warp tile 64x64, BM=BN=128, BK=64, 2-stage cp.async, 2 CTAs/SM.
// mode bits: 1 = fp32 Cf, 2 = fp16 perm32(col) Ch, 32 = fp16 plain Ch,
//            4 = fp16 vT layout via smem-staged coalesced stores
// ---------------------------------------------------------------------------
#define HBK    64
#define H_LDH  96
#define HSTAGE (256*H_LDH)
#define HGEMM_SMEM (2*HSTAGE*2)           // 98304 bytes
#define VSTG_LD 136

__device__ __forceinline__ void h_load_stage(
    __half* As, __half* Bs,
    const __half* __restrict__ Ab, const __half* __restrict__ Bb,
    int k0, int K, int tid)
{
#pragma unroll
    for (int i = 0; i < 8; i++) {
        int c = tid + 128 * i;
        int r = c >> 3, off = (c & 7) * 8;
        cp_async16(As + r * H_LDH + off, Ab + (size_t)r * K + k0 + off);
    }
#pragma unroll
    for (int i = 0; i < 8; i++) {
        int c = tid + 128 * i;
        int r = c >> 3, off = (c & 7) * 8;
        cp_async16(Bs + r * H_LDH + off, Bb + (size_t)r * K + k0 + off);
    }
}

__device__ __forceinline__ void f16_body(
    int N, int K,
    const __half* __restrict__ A, const __half* __restrict__ Bt,
    const float* __restrict__ bias,
    float* __restrict__ Cf, __half* __restrict__ Ch, int mode,
    int bx, int by, __half* hsm)
{
    const int tid  = threadIdx.x;
    const int warp = tid >> 5, lane = tid & 31;
    const int wm   = (warp >> 1) * 64;
    const int wn   = (warp & 1) * 64;
    const int g    = lane >> 2;
    const int tg   = lane & 3;

    const __half* Ab = A  + (size_t)(by * 128) * K;
    const __half* Bb = Bt + (size_t)(bx * 128) * K;

    float acc[4][8][4];
#pragma unroll
    for (int mt = 0; mt < 4; mt++)
#pragma unroll
        for (int nt = 0; nt < 8; nt++)
#pragma unroll
            for (int i = 0; i < 4; i++) acc[mt][nt][i] = 0.f;

    h_load_stage(hsm, hsm + 128 * H_LDH, Ab, Bb, 0, K, tid);
    cp_commit();
    if (HBK < K)
        h_load_stage(hsm + HSTAGE, hsm + HSTAGE + 128 * H_LDH, Ab, Bb, HBK, K, tid);
    cp_commit();

    int rs = 0;
    for (int k0 = 0; k0 < K; k0 += HBK) {
        cp_wait1();
        __syncthreads();

        __half* As = hsm + rs * HSTAGE;
        __half* Bs = As + 128 * H_LDH;

#pragma unroll
        for (int kb = 0; kb < 2; kb++) {
            uint4 aL[4], aH[4];
#pragma unroll
            for (int mt = 0; mt < 4; mt++) {
                aL[mt] = *(const uint4*)(As + (wm + mt * 16 + g)     * H_LDH + kb * 32 + 8 * tg);
                aH[mt] = *(const uint4*)(As + (wm + mt * 16 + g + 8) * H_LDH + kb * 32 + 8 * tg);
            }
#pragma unroll
            for (int nt = 0; nt < 8; nt++) {
                uint4 bv = *(const uint4*)(Bs + (wn + nt * 8 + g) * H_LDH + kb * 32 + 8 * tg);
#pragma unroll
                for (int mt = 0; mt < 4; mt++) {
                    mma_f16(acc[mt][nt], aL[mt].x, aH[mt].x, aL[mt].y, aH[mt].y, bv.x, bv.y);
                    mma_f16(acc[mt][nt], aL[mt].z, aH[mt].z, aL[mt].w, aH[mt].w, bv.z, bv.w);
                }
            }
        }

        __syncthreads();
        int kl = k0 + 2 * HBK;
        if (kl < K)
            h_load_stage(As, Bs, Ab, Bb, kl, K, tid);
        cp_commit();
        rs ^= 1;
    }

    if (mode & 4) {
        // vT epilogue: stage [128 d][perm32(s)] fp16 tile, then coalesce
        __half* stg = hsm;
#pragma unroll
        for (int mt = 0; mt < 4; mt++) {
            int sl_lo = wm + mt * 16 + g;
            int sl_hi = sl_lo + 8;
            int ps_lo = perm32(sl_lo), ps_hi = perm32(sl_hi);
#pragma unroll
            for (int nt = 0; nt < 8; nt++) {
                int cl = wn + nt * 8 + 2 * tg;
                float b0 = bias[bx * 128 + cl], b1 = bias[bx * 128 + cl + 1];
                stg[(cl)     * VSTG_LD + ps_lo] = __float2half(acc[mt][nt][0] + b0);
                stg[(cl + 1) * VSTG_LD + ps_lo] = __float2half(acc[mt][nt][1] + b1);
                stg[(cl)     * VSTG_LD + ps_hi] = __float2half(acc[mt][nt][2] + b0);
                stg[(cl + 1) * VSTG_LD + ps_hi] = __float2half(acc[mt][nt][3] + b1);
            }
        }
        __syncthreads();
        int bb = (by * 128) >> 11;
        int s0 = (by * 128) & (SEQ - 1);
        __half* vbase = Ch + ((size_t)bb * N + bx * 128) * SEQ + s0;
#pragma unroll
        for (int i = 0; i < 16; i++) {
            int c = tid + 128 * i;
            int cl = c >> 4, off = (c & 15) * 8;
            *(uint4*)(vbase + (size_t)cl * SEQ + off) =
                *(const uint4*)(stg + cl * VSTG_LD + off);
        }
        return;
    }

#pragma unroll
    for (int mt = 0; mt < 4; mt++) {
        int r_lo = by * 128 + wm + mt * 16 + g;
        int r_hi = r_lo + 8;
#pragma unroll
        for (int nt = 0; nt < 8; nt++) {
            int col = bx * 128 + wn + nt * 8 + 2 * tg;
            float b0 = bias[col], b1 = bias[col + 1];
            float v00 = acc[mt][nt][0] + b0, v01 = acc[mt][nt][1] + b1;
            float v10 = acc[mt][nt][2] + b0, v11 = acc[mt][nt][3] + b1;
            if (mode & 1) {
                *(float2*)(&Cf[(size_t)r_lo * N + col]) = make_float2(v00, v01);
                *(float2*)(&Cf[(size_t)r_hi * N + col]) = make_float2(v10, v11);
            }
            if (mode & 2) {
                int pc = perm32(col);
                *(__half2*)(&Ch[(size_t)r_lo * N + pc]) = __floats2half2_rn(v00, v01);
                *(__half2*)(&Ch[(size_t)r_hi * N + pc]) = __floats2half2_rn(v10, v11);
            }
            if (mode & 32) {
                *(__half2*)(&Ch[(size_t)r_lo * N + col]) = __floats2half2_rn(v00, v01);
                *(__half2*)(&Ch[(size_t)r_hi * N + col]) = __floats2half2_rn(v10, v11);
            }
        }
    }
}

// generic single-GEMM wrapper (UQ, WO)
__global__ __launch_bounds__(128, 2) void f16_gemm(
    int M, int N, int K,
    const __half* __restrict__ A, const __half* __restrict__ Bt,
    const float* __restrict__ bias,
    float* __restrict__ Cf, __half* __restrict__ Ch, int mode)
{
    extern __shared__ __half hsm[];
    f16_body(N, K, A, Bt, bias, Cf, Ch, mode, blockIdx.x, blockIdx.y, hsm);
}

// fused DKV + KR + DQ (all A = h16, K = 2048).  grid.x = 32:
//   bx 0-3  : DKV (N=512,  mode 3 -> cKV fp32 + cKV16 perm)
//   bx 4-19 : KR  (N=2048, mode 1 -> kr fp32)
//   bx 20-31: DQ  (N=1536, mode 2 -> cQ16 perm)
__global__ __launch_bounds__(128, 2) void f16_gemm_h3(
    const __half* __restrict__ A,
    const __half* __restrict__ wDKV, const __half* __restrict__ wKR,
    const __half* __restrict__ wDQ,
    const float* __restrict__ bDKV, const float* __restrict__ bKR,
    const float* __restrict__ bDQ,
    float* __restrict__ cKV, __half* __restrict__ cKV16,
    float* __restrict__ kr, __half* __restrict__ cQ16)
{
    extern __shared__ __half hsm[];
    int bx = blockIdx.x, by = blockIdx.y;
    if (bx < 4) {
        f16_body(DKV, DMODEL, A, wDKV, bDKV, cKV, cKV16, 3, bx, by, hsm);
    } else if (bx < 20) {
        f16_body(DMODEL, DMODEL, A, wKR, bKR, kr, (__half*)0, 1, bx - 4, by, hsm);
    } else {
        f16_body(DQ, DMODEL, A, wDQ, bDQ, (float*)0, cQ16, 2, bx - 20, by, hsm);
    }
}

// fused UK + UV (A = cKV16, K = 512).  grid.x = 32:
//   bx 0-15 : UK (mode 32 -> kC16 plain)
//   bx 16-31: UV (mode 4  -> vT staged)
__global__ __launch_bounds__(128, 2) void f16_gemm_ukuv(
    const __half* __restrict__ A,
    const __half* __restrict__ wUK, const __half* __restrict__ wUV,
    const float* __restrict__ bUK, const float* __restrict__ bUV,
    __half* __restrict__ kC16, __half* __restrict__ vT)
{
    extern __shared__ __half hsm[];
    int bx = blockIdx.x, by = blockIdx.y;
    if (bx < 16) {
        f16_body(DMODEL, DKV, A, wUK, bUK, (float*)0, kC16, 32, bx, by, hsm);
    } else {
        f16_body(DMODEL, DKV, A, wUV, bUV, (float*)0, vT, 4, bx - 16, by, hsm);
    }
}

// ---------------------------------------------------------------------------
// Pack q (fp16 in, fp16 out, scaled, perm32 on k-dim)
// ---------------------------------------------------------------------------
__global__ __launch_bounds__(256) void pack_q_kernel(
    const __half* __restrict__ qC, const float2* __restrict__ rope,
    __half* __restrict__ q)
{
    int gid = blockIdx.x * blockDim.x + threadIdx.x;
    int i = gid & 63;
    int s = (gid >> 6) & (SEQ - 1);
    int h = (gid >> 17) & (NHEADS - 1);
    int b = gid >> 21;

    const __half2* src = (const __half2*)(qC + ((size_t)(b * SEQ + s)) * DMODEL + h * HDIM);
    float2 x = __half22float2(src[i]);

    float2 cssn = rope[s * 64 + i];
    float cs = cssn.x, sn = cssn.y;

    __half* dst = q + (((size_t)(b * NHEADS + h)) * SEQ + s) * QKDIM;
    dst[perm32(2 * i)]       = __float2half(x.x * SCALE);
    dst[perm32(2 * i + 1)]   = __float2half(x.y * SCALE);
    dst[perm32(128 + 2 * i)] = __float2half((x.x * cs - x.y * sn) * SCALE);
    dst[perm32(129 + 2 * i)] = __float2half((x.x * sn + x.y * cs) * SCALE);
}

// ---------------------------------------------------------------------------
// Pack k (fp16 raw in, fp32 kr in, fp16 out, perm32 on k-dim)
// ---------------------------------------------------------------------------
__global__ __launch_bounds__(256) void pack_k_kernel(
    const __half* __restrict__ kC, const float* __restrict__ kr,
    const float2* __restrict__ rope, __half* __restrict__ k)
{
    int gid = blockIdx.x * blockDim.x + threadIdx.x;
    int i = gid & 63;
    int s = (gid >> 6) & (SEQ - 1);
    int h = (gid >> 17) & (NHEADS - 1);
    int b = gid >> 21;

    size_t soff = ((size_t)(b * SEQ + s)) * DMODEL + h * HDIM;
    const __half2* raw = (const __half2*)(kC + soff);
    float2 x = __half22float2(raw[i]);
    float2 rot = *(const float2*)(kr + soff + 2 * i);

    float2 cssn = rope[s * 64 + i];
    float cs = cssn.x, sn = cssn.y;

    __half* dst = k + (((size_t)(b * NHEADS + h)) * SEQ + s) * QKDIM;
    dst[perm32(2 * i)]       = __float2half(x.x);
    dst[perm32(2 * i + 1)]   = __float2half(x.y);
    dst[perm32(128 + 2 * i)] = __float2half(rot.x * cs - rot.y * sn);
    dst[perm32(129 + 2 * i)] = __float2half(rot.x * sn + rot.y * cs);
}

// ---------------------------------------------------------------------------
// FP16 flash attention.  BM=128 (8 M-warps x 16 rows), BN=64, 256 threads.
// Q and P in registers.  K and V double-buffered: 2 syncs/iter.  (R13)
// ---------------------------------------------------------------------------
#define K_LDH 288
#define V_LDH 96
#define KBUF  (64*K_LDH)
#define VBUF  (128*V_LDH)
#define FL_SMEM ((2*KBUF + 2*VBUF) * 2)   // 122880 bytes

__global__ __launch_bounds__(256, 1) void flash_f16(
    const __half* __restrict__ q,
    const __half* __restrict__ kk,
    const __half* __restrict__ vT,
    __half* __restrict__ ctx16)
{
    extern __shared__ __half smh[];
    __half* ksb = smh;
    __half* vsb = smh + 2 * KBUF;

    const int tid  = threadIdx.x;
    const int warp = tid >> 5, lane = tid & 31;
    const int g    = lane >> 2;
    const int tg   = lane & 3;
    const int wm   = warp * 16;

    const int qt = 15 - blockIdx.x;
    const int bh = blockIdx.y;
    const int b = bh >> 4, h = bh & 15;
    const int kmax = 2 * qt + 2;

    const __half* vtb_base = vT + ((size_t)b * DMODEL + h * HDIM) * SEQ;
    const __half* kbh      = kk + ((size_t)bh * SEQ) * QKDIM;

    const int rg0 = qt * 128 + wm + g;
    const int rg1 = rg0 + 8;
    uint4 qlo[8], qhi[8];
    {
        const uint4* q0 = (const uint4*)(q + ((size_t)bh * SEQ + rg0) * QKDIM) + tg;
        const uint4* q1 = (const uint4*)(q + ((size_t)bh * SEQ + rg1) * QKDIM) + tg;
#pragma unroll
        for (int kb = 0; kb < 8; kb++) {
            qlo[kb] = q0[kb * 4];
            qhi[kb] = q1[kb * 4];
        }
    }

#pragma unroll
    for (int st = 0; st < 2; st++) {
        if (st < kmax) {
            const __half* kb = kbh + (size_t)(st * 64) * QKDIM;
            __half* ks = ksb + st * KBUF;
#pragma unroll
            for (int i = 0; i < 8; i++) {
                int c = tid + 256 * i;
                int r = c >> 5, off = (c & 31) * 8;
                cp_async16(ks + r * K_LDH + off, kb + (size_t)r * QKDIM + off);
            }
            const __half* vb = vtb_base + st * 64;
            __half* vs = vsb + st * VBUF;
#pragma unroll
            for (int i = 0; i < 4; i++) {
                int c = tid + 256 * i;
                int r = c >> 3, off = (c & 7) * 8;
                cp_async16(vs + r * V_LDH + off, vb + (size_t)r * SEQ + off);
            }
        }
        cp_commit();
    }

    float m0 = -1e30f, m1 = -1e30f, l0 = 0.f, l1 = 0.f;
    float oacc[16][4];
#pragma unroll
    for (int nt = 0; nt < 16; nt++)
#pragma unroll
        for (int i = 0; i < 4; i++) oacc[nt][i] = 0.f;

    for (int kt = 0; kt < kmax; kt++) {
        cp_wait1();
        __syncthreads();

        const __half* ks = ksb + (kt & 1) * KBUF;
        const __half* vs = vsb + (kt & 1) * VBUF;

        float sacc[8][4];
#pragma unroll
        for (int nt = 0; nt < 8; nt++)
#pragma unroll
            for (int i = 0; i < 4; i++) sacc[nt][i] = 0.f;

#pragma unroll
        for (int kb = 0; kb < 8; kb++) {
            uint4 L = qlo[kb], H = qhi[kb];
#pragma unroll
            for (int nt = 0; nt < 8; nt++) {
                uint4 kv = *(const uint4*)(ks + (8 * nt + g) * K_LDH + kb * 32 + 8 * tg);
                mma_f16(sacc[nt], L.x, H.x, L.y, H.y, kv.x, kv.y);
                mma_f16(sacc[nt], L.z, H.z, L.w, H.w, kv.z, kv.w);
            }
        }

        if (kt >= 2 * qt) {
            int cb = kt * 64 + 2 * tg;
#pragma unroll
            for (int nt = 0; nt < 8; nt++) {
                int c0 = cb + 8 * nt, c1 = c0 + 1;
                if (c0 > rg0) sacc[nt][0] = -1e30f;
                if (c1 > rg0) sacc[nt][1] = -1e30f;
                if (c0 > rg1) sacc[nt][2] = -1e30f;
                if (c1 > rg1) sacc[nt][3] = -1e30f;
            }
        }

        float tA = -1e30f, tB = -1e30f;
#pragma unroll
        for (int nt = 0; nt < 8; nt++) {
            tA = fmaxf(tA, fmaxf(sacc[nt][0], sacc[nt][1]));
            tB = fmaxf(tB, fmaxf(sacc[nt][2], sacc[nt][3]));
        }
        tA = fmaxf(tA, __shfl_xor_sync(0xffffffffu, tA, 1));
        tA = fmaxf(tA, __shfl_xor_sync(0xffffffffu, tA, 2));
        tB = fmaxf(tB, __shfl_xor_sync(0xffffffffu, tB, 1));
        tB = fmaxf(tB, __shfl_xor_sync(0xffffffffu, tB, 2));

        float mn0 = fmaxf(m0, tA), mn1 = fmaxf(m1, tB);
        float f0 = __expf(m0 - mn0), f1 = __expf(m1 - mn1);
        m0 = mn0; m1 = mn1;

        float sum0 = 0.f, sum1 = 0.f;
        uint32_t ph01[8], ph23[8];
#pragma unroll
        for (int nt = 0; nt < 8; nt++) {
            float p0 = __expf(sacc[nt][0] - mn0);
            float p1 = __expf(sacc[nt][1] - mn0);
            float p2 = __expf(sacc[nt][2] - mn1);
            float p3 = __expf(sacc[nt][3] - mn1);
            sum0 += p0 + p1;
            sum1 += p2 + p3;
            ph01[nt] = h2_as_u32(__floats2half2_rn(p0, p1));
            ph23[nt] = h2_as_u32(__floats2half2_rn(p2, p3));
        }
        sum0 += __shfl_xor_sync(0xffffffffu, sum0, 1);
        sum0 += __shfl_xor_sync(0xffffffffu, sum0, 2);
        sum1 += __shfl_xor_sync(0xffffffffu, sum1, 1);
        sum1 += __shfl_xor_sync(0xffffffffu, sum1, 2);
        l0 = l0 * f0 + sum0;
        l1 = l1 * f1 + sum1;

#pragma unroll
        for (int nt = 0; nt < 16; nt++) {
            oacc[nt][0] *= f0; oacc[nt][1] *= f0;
            oacc[nt][2] *= f1; oacc[nt][3] *= f1;
        }
#pragma unroll
        for (int kb = 0; kb < 2; kb++) {
            uint32_t aL0 = ph01[4 * kb + 0], aL1 = ph23[4 * kb + 0];
            uint32_t aL2 = ph01[4 * kb + 1], aL3 = ph23[4 * kb + 1];
            uint32_t aH0 = ph01[4 * kb + 2], aH1 = ph23[4 * kb + 2];
            uint32_t aH2 = ph01[4 * kb + 3], aH3 = ph23[4 * kb + 3];
#pragma unroll
            for (int nt = 0; nt < 16; nt++) {
                uint4 vv = *(const uint4*)(vs + (8 * nt + g) * V_LDH + kb * 32 + 8 * tg);
                mma_f16(oacc[nt], aL0, aL1, aL2, aL3, vv.x, vv.y);
                mma_f16(oacc[nt], aH0, aH1, aH2, aH3, vv.z, vv.w);
            }
        }

        __syncthreads();

        if (kt + 2 < kmax) {
            const __half* kb = kbh + (size_t)((kt + 2) * 64) * QKDIM;
            __half* ksn = ksb + (kt & 1) * KBUF;
#pragma unroll
            for (int i = 0; i < 8; i++) {
                int c = tid + 256 * i;
                int r = c >> 5, off = (c & 31) * 8;
                cp_async16(ksn + r * K_LDH + off, kb + (size_t)r * QKDIM + off);
            }
            const __half* vb = vtb_base + (kt + 2) * 64;
            __half* vsn = vsb + (kt & 1) * VBUF;
#pragma unroll
            for (int i = 0; i < 4; i++) {
                int c = tid + 256 * i;
                int r = c >> 3, off = (c & 7) * 8;
                cp_async16(vsn + r * V_LDH + off, vb + (size_t)r * SEQ + off);
            }
        }
        cp_commit();
    }

    float inv0 = 1.f / l0, inv1 = 1.f / l1;
    __half* o0 = ctx16 + ((size_t)b * SEQ + rg0) * DMODEL + h * HDIM;
    __half* o1 = ctx16 + ((size_t)b * SEQ + rg1) * DMODEL + h * HDIM;
#pragma unroll
    for (int nt = 0; nt < 16; nt++) {
        int c = 8 * nt + 2 * tg;
        int pc = perm32(c);
        *(__half2*)(o0 + pc) = __floats2half2_rn(oacc[nt][0] * inv0, oacc[nt][1] * inv0);
        *(__half2*)(o1 + pc) = __floats2half2_rn(oacc[nt][2] * inv1, oacc[nt][3] * inv1);
    }
}

// ---------------------------------------------------------------------------
// Launch
// ---------------------------------------------------------------------------
extern "C" void kernel_launch(void* const* d_in, const int* in_sizes, int n_in,
                              void* d_out, int out_size)
{
    const float* h     = (const float*)d_in[0];
    const float* W_DKV = (const float*)d_in[1];
    const float* b_DKV = (const float*)d_in[2];
    const float* W_UK  = (const float*)d_in[3];
    const float* b_UK  = (const float*)d_in[4];
    const float* W_UV  = (const float*)d_in[5];
    const float* b_UV  = (const float*)d_in[6];
    const float* W_DQ  = (const float*)d_in[7];
    const float* b_DQ  = (const float*)d_in[8];
    const float* W_UQ  = (const float*)d_in[9];
    const float* b_UQ  = (const float*)d_in[10];
    const float* W_KR  = (const float*)d_in[11];
    const float* b_KR  = (const float*)d_in[12];
    const float* W_O   = (const float*)d_in[13];
    const float* b_O   = (const float*)d_in[14];

    float* out = (float*)d_out;
    float* cKV = out + OUT_SZ;
    float* kr  = cKV + CKV_SZ;

    float2* p_rope;
    __half *p_vT, *p_q, *p_k;
    __half *p_h16, *p_cKV16, *p_cQ16, *p_ctx16, *p_qC16, *p_kC16;
    __half *p_wDKV, *p_wKR, *p_wDQ, *p_wUQ, *p_wUK, *p_wUV, *p_wWO;
    cudaGetSymbolAddress((void**)&p_vT,    g_vT);
    cudaGetSymbolAddress((void**)&p_q,     g_q);
    cudaGetSymbolAddress((void**)&p_k,     g_k);
    cudaGetSymbolAddress((void**)&p_rope,  g_rope);
    cudaGetSymbolAddress((void**)&p_h16,   g_h16);
    cudaGetSymbolAddress((void**)&p_cKV16, g_cKV16);
    cudaGetSymbolAddress((void**)&p_cQ16,  g_cQ16);
    cudaGetSymbolAddress((void**)&p_ctx16, g_ctx16);
    cudaGetSymbolAddress((void**)&p_qC16,  g_qC16);
    cudaGetSymbolAddress((void**)&p_kC16,  g_kC16);
    cudaGetSymbolAddress((void**)&p_wDKV,  g_wDKV);
    cudaGetSymbolAddress((void**)&p_wKR,   g_wKR);
    cudaGetSymbolAddress((void**)&p_wDQ,   g_wDQ);
    cudaGetSymbolAddress((void**)&p_wUQ,   g_wUQ);
    cudaGetSymbolAddress((void**)&p_wUK,   g_wUK);
    cudaGetSymbolAddress((void**)&p_wUV,   g_wUV);
    cudaGetSymbolAddress((void**)&p_wWO,   g_wWO);

    cudaFuncSetAttribute(f16_gemm,
                         cudaFuncAttributeMaxDynamicSharedMemorySize, HGEMM_SMEM);
    cudaFuncSetAttribute(f16_gemm_h3,
                         cudaFuncAttributeMaxDynamicSharedMemorySize, HGEMM_SMEM);
    cudaFuncSetAttribute(f16_gemm_ukuv,
                         cudaFuncAttributeMaxDynamicSharedMemorySize, HGEMM_SMEM);
    cudaFuncSetAttribute(flash_f16,
                         cudaFuncAttributeMaxDynamicSharedMemorySize, FL_SMEM);

    int pack_threads = BATCH * NHEADS * SEQ * 64;

    // setup (all independent, cheap)
    rope_table_kernel<<<(SEQ * 64) / 256, 256>>>(p_rope);
    conv_h_kernel<<<(ROWS * DMODEL) / 256, 256>>>(h, p_h16);
    conv_wt_kernel<<<dim3(DKV/32,    DMODEL/32), 256>>>(W_DKV, p_wDKV, DMODEL, DKV);
    conv_wt_kernel<<<dim3(DMODEL/32, DMODEL/32), 256>>>(W_KR,  p_wKR,  DMODEL, DMODEL);
    conv_wt_kernel<<<dim3(DQ/32,     DMODEL/32), 256>>>(W_DQ,  p_wDQ,  DMODEL, DQ);
    conv_wt_kernel<<<dim3(DMODEL/32, DQ/32),     256>>>(W_UQ, p_wUQ, DQ,  DMODEL);
    conv_wt_kernel<<<dim3(DMODEL/32, DKV/32),    256>>>(W_UK, p_wUK, DKV, DMODEL);
    conv_wt_kernel<<<dim3(DMODEL/32, DKV/32),    256>>>(W_UV, p_wUV, DKV, DMODEL);
    conv_wt_kernel<<<dim3(DMODEL/32, DMODEL/32), 256>>>(W_O,  p_wWO, DMODEL, DMODEL);

    // fused DKV + KR + DQ
    f16_gemm_h3<<<dim3(32, ROWS/128), 128, HGEMM_SMEM>>>(
        p_h16, p_wDKV, p_wKR, p_wDQ, b_DKV, b_KR, b_DQ,
        cKV, p_cKV16, kr, p_cQ16);
    // UQ
    f16_gemm<<<dim3(DMODEL/128, ROWS/128), 128, HGEMM_SMEM>>>(ROWS, DMODEL, DQ, p_cQ16, p_wUQ, b_UQ, (float*)0, p_qC16, 32);
    pack_q_kernel<<<pack_threads / 256, 256>>>(p_qC16, p_rope, p_q);
    // fused UK + UV
    f16_gemm_ukuv<<<dim3(32, ROWS/128), 128, HGEMM_SMEM>>>(
        p_cKV16, p_wUK, p_wUV, b_UK, b_UV, p_kC16, p_vT);
    pack_k_kernel<<<pack_threads / 256, 256>>>(p_kC16, kr, p_rope, p_k);
    // attention
    flash_f16<<<dim3(16, BATCH*NHEADS), 256, FL_SMEM>>>(p_q, p_k, p_vT, p_ctx16);
    // output projection
    f16_gemm<<<dim3(DMODEL/128, ROWS/128), 128, HGEMM_SMEM>>>(ROWS, DMODEL, DMODEL, p_ctx16, p_wWO, b_O, out, (__half*)0, 1);
}